// round 16
// baseline (speedup 1.0000x reference)
#include <cuda_runtime.h>
#include <cuda_bf16.h>

// CoverageLoss, fused single-kernel, fully closed form (no boundary read).
//
// Boundary samples are 4 axis-aligned uniform segments of the box with
// parallel coordinate lins[j] = linspace(0,1,100)[j] ~= j/99 (1-ulp exact).
// min over an edge separates: (perp)^2 + min_j (par - j*w/99)^2 with
// j = clamp(round(t*99), 0, 99)  ->  one F2I + one FFMA, no table, so the
// boundary tensor is never loaded (no cold DRAM fetch, no entry barrier).
//
// Converged configuration (measured optimum across R7-R15):
//   - 128 blocks x 256 threads, thread = (box, 4 points), single wave
//   - min over 64 boxes: warp shuffle (32) + one smem pair exchange
//   - tail: thread-0 tree reduce (LDS.128 + pairwise min/add) +
//     contended atomicAdd(g_sum) + acq_rel counter atomic (fence fused);
//     last block writes out and resets scratch (graph-replay safe)

#define NPTS  2048
#define NBOX  64
#define PPTH  4                       // points per thread
#define NBLK  (NPTS / (PPTH * 4))     // 128 blocks, 16 points per block
#define NLIN  100

__device__ float        g_sum = 0.0f;   // static zero-init; reset by last block
__device__ unsigned int g_cnt = 0u;

__global__ __launch_bounds__(256)
void cl_fused_kernel(const float* __restrict__ pred,
                     const float* __restrict__ frag,
                     float* __restrict__ out) {
    __shared__ float4 s_red[8];       // one float4 row per warp (PPTH == 4)

    const int tid = threadIdx.x;
    const int b   = tid & 63;         // box index
    const int pl  = tid >> 6;         // point-slot 0..3 (two warps per slot)

    // ---- box constants (hoisted across 4 points, incl. both MUFU rcp) ----
    const float4 pr = ((const float4*)pred)[b];
    const float lx = pr.x, ly = pr.y, hx = pr.z, hy = pr.w;
    const float wx = hx - lx;
    const float wy = hy - ly;
    const float ex = wx + lx;          // right-edge x as the reference computes it
    const float ey = wy + ly;          // top-edge y
    const float c99rwx = 99.0f * __frcp_rn(wx);
    const float c99rwy = 99.0f * __frcp_rn(wy);
    const float wx99 = wx * (1.0f / 99.0f);   // grid step along x
    const float wy99 = wy * (1.0f / 99.0f);   // grid step along y

    // ---- 4 fragment points, contiguous: 2x float4 loads ----
    const int pbase = blockIdx.x * 16 + pl * PPTH;
    const float4 f01 = ((const float4*)frag)[pbase / 2];
    const float4 f23 = ((const float4*)frag)[pbase / 2 + 1];
    float fxs[PPTH] = {f01.x, f01.z, f23.x, f23.z};
    float fys[PPTH] = {f01.y, f01.w, f23.y, f23.w};

    float vals[PPTH];
#pragma unroll
    for (int i = 0; i < PPTH; i++) {
        const float fx = fxs[i], fy = fys[i];
        const bool inside = (fx >= lx) && (fy >= ly) && (hx >= fx) && (hy >= fy);

        // vertical edges: x fixed, nearest y sample (F2I of NaN -> 0, clamp safe)
        const float dyl = fy - ly;
        const int j = min(max(__float2int_rn(dyl * c99rwy), 0), NLIN - 1);
        float d = fmaf((float)-j, wy99, dyl);     // fy - (ly + j*wy/99)
        const float mdy2 = d * d;
        const float dxl = fx - lx;
        const float dxh = fx - ex;
        const float dvert = fminf(dxl * dxl, dxh * dxh) + mdy2;

        // horizontal edges: y fixed, nearest x sample
        const int k = min(max(__float2int_rn(dxl * c99rwx), 0), NLIN - 1);
        d = fmaf((float)-k, wx99, dxl);           // fx - (lx + k*wx/99)
        const float mdx2 = d * d;
        const float dyh = fy - ey;
        const float dhorz = fminf(dyl * dyl, dyh * dyh) + mdx2;

        vals[i] = inside ? 0.0f : fminf(dvert, dhorz);
    }

    // ---- min over 64 boxes: shuffle within warp (32 boxes), pair via shared ----
#pragma unroll
    for (int o = 16; o > 0; o >>= 1) {
#pragma unroll
        for (int i = 0; i < PPTH; i++)
            vals[i] = fminf(vals[i], __shfl_xor_sync(0xffffffffu, vals[i], o));
    }
    if ((tid & 31) == 0)
        s_red[tid >> 5] = make_float4(vals[0], vals[1], vals[2], vals[3]);
    __syncthreads();

    // ---- tail: tree reduce (LDS.128, pairwise), atomic sum + acq_rel counter ----
    if (tid == 0) {
        float4 r0 = s_red[0], r1 = s_red[1];   // slot 0: warps 0/1
        float4 r2 = s_red[2], r3 = s_red[3];   // slot 1
        float4 r4 = s_red[4], r5 = s_red[5];   // slot 2
        float4 r6 = s_red[6], r7 = s_red[7];   // slot 3
        float4 m0 = make_float4(fminf(r0.x, r1.x), fminf(r0.y, r1.y),
                                fminf(r0.z, r1.z), fminf(r0.w, r1.w));
        float4 m1 = make_float4(fminf(r2.x, r3.x), fminf(r2.y, r3.y),
                                fminf(r2.z, r3.z), fminf(r2.w, r3.w));
        float4 m2 = make_float4(fminf(r4.x, r5.x), fminf(r4.y, r5.y),
                                fminf(r4.z, r5.z), fminf(r4.w, r5.w));
        float4 m3 = make_float4(fminf(r6.x, r7.x), fminf(r6.y, r7.y),
                                fminf(r6.z, r7.z), fminf(r6.w, r7.w));
        float4 a0 = make_float4(m0.x + m1.x, m0.y + m1.y, m0.z + m1.z, m0.w + m1.w);
        float4 a1 = make_float4(m2.x + m3.x, m2.y + m3.y, m2.z + m3.z, m2.w + m3.w);
        float s = ((a0.x + a1.x) + (a0.y + a1.y)) + ((a0.z + a1.z) + (a0.w + a1.w));

        atomicAdd(&g_sum, s);
        // release: g_sum contribution visible before counter tick;
        // acquire: last block's read-back below is ordered after all ticks.
        unsigned done;
        asm volatile("atom.add.acq_rel.gpu.global.u32 %0, [%1], %2;"
                     : "=r"(done) : "l"(&g_cnt), "r"(1u) : "memory");
        if (done == NBLK - 1) {
            float tot = atomicAdd(&g_sum, 0.0f);   // atomic read-back
            out[0] = tot * (1.0f / 64.0f);         // / FP
            g_sum = 0.0f;                          // restore invariant for replay
            g_cnt = 0u;
        }
    }
}

extern "C" void kernel_launch(void* const* d_in, const int* in_sizes, int n_in,
                              void* d_out, int out_size) {
    const float* pred = (const float*)d_in[0];   // [64,4]
    const float* frag = (const float*)d_in[1];   // [32,64,2]
    cl_fused_kernel<<<NBLK, 256>>>(pred, frag, (float*)d_out);
}